// round 6
// baseline (speedup 1.0000x reference)
#include <cuda_runtime.h>
#include <math.h>
#include <stdint.h>

#define B_  64
#define T_  512
#define IN_ 1024
#define H_  1024
#define L_  5

#define NBLK 128   // persistent CTAs, 1 per SM
#define TPB  512   // 16 warps, 4 per SMSP

typedef unsigned long long ull;

// smem geometry (floats)
#define SP      260                   // tile pitch (float4-aligned, conflict-free)
#define ST_ROWS 64
#define WT_ROWS 16
#define WT_OFFS (ST_ROWS * SP)        // 16640
#define BUFSZ   ((ST_ROWS + WT_ROWS) * SP)   // 20800 floats
#define SMEM_FLOATS (2 * BUFSZ)       // 41600 floats = 166400 B
#define PP      1025                  // partial pitch per gate-col (16*64 + 1)

// Static device scratch:
__device__ float g_xw[(size_t)B_ * T_ * 2 * H_];   // [whx|wtx], time-major
__device__ float g_state[2][B_ * H_];              // double-buffered state
__device__ unsigned g_bar_arrive = 0;
__device__ unsigned g_bar_gen    = 0;

// ---- packed fp32x2 helpers (sm_103a FFMA2) --------------------------------
__device__ __forceinline__ void ffma2(ull& d, ull a, ull b) {
    asm("fma.rn.f32x2 %0, %1, %2, %0;" : "+l"(d) : "l"(a), "l"(b));
}
__device__ __forceinline__ ull packff(float x, float y) {
    ull r; asm("mov.b64 %0, {%1, %2};" : "=l"(r) : "f"(x), "f"(y)); return r;
}
__device__ __forceinline__ float f32x2_sum(ull v) {
    union { ull u; float2 f; } c; c.u = v; return c.f.x + c.f.y;
}

// ---- cp.async helpers -----------------------------------------------------
__device__ __forceinline__ void cp16_cg(uint32_t dst, const void* src) {
    asm volatile("cp.async.cg.shared.global [%0], [%1], 16;" :: "r"(dst), "l"(src) : "memory");
}
__device__ __forceinline__ void cp16_ca(uint32_t dst, const void* src) {
    asm volatile("cp.async.ca.shared.global [%0], [%1], 16;" :: "r"(dst), "l"(src) : "memory");
}
#define CP_COMMIT() asm volatile("cp.async.commit_group;" ::: "memory")
#define CP_WAIT0()  asm volatile("cp.async.wait_group 0;" ::: "memory")

// ---------------------------------------------------------------------------
// Input GEMM with FFMA2 (unchanged from R5)
// ---------------------------------------------------------------------------
__global__ __launch_bounds__(256) void xw_gemm_kernel(
    const float* __restrict__ x,
    const float* __restrict__ w_h,
    const float* __restrict__ w_t)
{
    __shared__ float As[8][132];
    __shared__ float Bs[8][132];

    const int jb  = blockIdx.x;
    const int rb  = blockIdx.y;
    const int tid = threadIdx.x;
    const int tx  = tid % 16;
    const int ty  = tid / 16;

    const int jbase = jb * 128;
    const float* W  = (jbase < H_) ? w_h : w_t;
    const int  joff = jbase % H_;

    ull acc2[8][4];
    #pragma unroll
    for (int i = 0; i < 8; i++)
        #pragma unroll
        for (int j = 0; j < 4; j++) acc2[i][j] = 0ull;

    const int arow = tid / 2;
    const int ak   = (tid % 2) * 4;
    const int r    = rb * 128 + arow;
    const int xrow = (r % B_) * T_ + (r / B_);
    const float* aptr = x + (size_t)xrow * IN_ + ak;

    const int bk = tid / 32;
    const int bj = (tid % 32) * 4;
    const float* bptr = W + (size_t)bk * H_ + joff + bj;

    for (int kt = 0; kt < IN_; kt += 8) {
        float4 av = *(const float4*)(aptr + kt);
        float4 bv = *(const float4*)(bptr + (size_t)kt * H_);
        __syncthreads();
        As[ak + 0][arow] = av.x;
        As[ak + 1][arow] = av.y;
        As[ak + 2][arow] = av.z;
        As[ak + 3][arow] = av.w;
        *(float4*)&Bs[bk][bj] = bv;
        __syncthreads();

        #pragma unroll
        for (int k = 0; k < 8; k++) {
            float a[8];
            #pragma unroll
            for (int i = 0; i < 8; i++) a[i] = As[k][ty * 8 + i];
            ulonglong2 bv0 = *(const ulonglong2*)&Bs[k][tx * 8];
            ulonglong2 bv1 = *(const ulonglong2*)&Bs[k][tx * 8 + 4];
            #pragma unroll
            for (int i = 0; i < 8; i++) {
                ull ap = packff(a[i], a[i]);
                ffma2(acc2[i][0], ap, bv0.x);
                ffma2(acc2[i][1], ap, bv0.y);
                ffma2(acc2[i][2], ap, bv1.x);
                ffma2(acc2[i][3], ap, bv1.y);
            }
        }
    }

    #pragma unroll
    for (int i = 0; i < 8; i++) {
        int rr = rb * 128 + ty * 8 + i;
        float* cp = g_xw + (size_t)rr * (2 * H_) + jbase + tx * 8;
        union { ull u; float2 f; } c0, c1, c2, c3;
        c0.u = acc2[i][0]; c1.u = acc2[i][1]; c2.u = acc2[i][2]; c3.u = acc2[i][3];
        *(float4*)(cp + 0) = make_float4(c0.f.x, c0.f.y, c1.f.x, c1.f.y);
        *(float4*)(cp + 4) = make_float4(c2.f.x, c2.f.y, c3.f.x, c3.f.y);
    }
}

// ---------------------------------------------------------------------------
// Grid-wide barrier (gpu-scope fence -> CCTL.IVALL keeps L1 coherent)
// ---------------------------------------------------------------------------
__device__ __forceinline__ void grid_sync_persistent()
{
    __syncthreads();
    if (threadIdx.x == 0) {
        volatile unsigned* genp = &g_bar_gen;
        unsigned my_gen = *genp;
        __threadfence();
        unsigned a = atomicAdd(&g_bar_arrive, 1u);
        if (a == NBLK - 1) {
            g_bar_arrive = 0;
            __threadfence();
            atomicAdd(&g_bar_gen, 1u);
        } else {
            while (*genp == my_gen) { }
            __threadfence();
        }
    }
    __syncthreads();
}

// ---------------------------------------------------------------------------
// Persistent recurrent kernel, K-split across 16 warps.
// CTA: 8 g-cols x 2 gates = 16 gate-cols, all 64 b-rows.
// Warp w: k-slice [tile*256 + w*16, +16); covers ALL 1024 outputs.
// Thread: 8 b (bgrp+8i) x 4 gate-cols (ggrp+4j), 32 f32x2 accumulators.
// Cross-warp reduction of 16 partials in smem, then fused epilogue.
// ---------------------------------------------------------------------------
__global__ __launch_bounds__(TPB) void rhn_persistent_kernel(
    const float* __restrict__ rh_w, const float* __restrict__ rh_b,
    const float* __restrict__ rt_w, const float* __restrict__ rt_b,
    float* __restrict__ out)
{
    extern __shared__ float smem[];
    const uint32_t smem_u32 = (uint32_t)__cvta_generic_to_shared(smem);

    const int tid  = threadIdx.x;
    const int warp = tid >> 5;           // 0..15
    const int lane = tid & 31;
    const int bgrp = lane >> 2;          // 0..7
    const int ggrp = lane & 3;           // 0..3
    const int ks   = warp * 16;          // k-slice base within a 256-k tile
    const int gb   = blockIdx.x;         // 0..127

    // cp.async mappings
    const int s_r  = tid >> 3;           // 0..63  (state row)
    const int s_c  = (tid & 7) * 32;     // col base, 8 float4 each
    const int w_r  = tid >> 5;           // 0..15  (weight smem row = gate-col)
    const int w_c  = (tid & 31) * 8;     // 2 float4 each

    const float* whbase = rh_w + (size_t)(gb * 8) * H_;  // +l*H*H
    const float* wtbase = rt_w + (size_t)(gb * 8) * H_;

    // weight global row for w_r: gate = w_r>>3, gq = w_r&7
    const int wg_gate = w_r >> 3;
    const int wg_gq   = w_r & 7;

    auto issue_s = [&](const float* scur, int kt, int buf) {
        const float* src = scur + (size_t)s_r * H_ + kt * 256 + s_c;
        uint32_t dst = smem_u32 + (uint32_t)(buf * BUFSZ + s_r * SP + s_c) * 4;
        #pragma unroll
        for (int ii = 0; ii < 8; ii++)
            cp16_cg(dst + ii * 16, src + ii * 4);
    };
    auto issue_w = [&](const float* wh, const float* wt, int kt, int buf) {
        const float* wrow = (wg_gate ? wt : wh) + (size_t)wg_gq * H_ + kt * 256 + w_c;
        uint32_t dst = smem_u32 + (uint32_t)(buf * BUFSZ + WT_OFFS + w_r * SP + w_c) * 4;
        cp16_ca(dst + 0,  wrow + 0);
        cp16_ca(dst + 16, wrow + 4);
    };

    // prologue: tile 0 of step 0
    issue_w(whbase, wtbase, 0, 0);
    issue_s(g_state[0], 0, 0);
    CP_COMMIT();

    int t = 0, l = 0;
    for (int step = 0; step < T_ * L_; step++) {
        const int pin = step & 1;
        const float* scur = g_state[pin];
        float*       snxt = g_state[pin ^ 1];
        const float* wh = whbase + (size_t)l * H_ * H_;
        const float* wt = wtbase + (size_t)l * H_ * H_;

        ull acc[8][4];
        #pragma unroll
        for (int i = 0; i < 8; i++)
            #pragma unroll
            for (int j = 0; j < 4; j++) acc[i][j] = 0ull;

        // ---- mainloop: 4 k-tiles of 256, double-buffered -------------------
        #pragma unroll
        for (int kt = 0; kt < 4; kt++) {
            CP_WAIT0();            // tile kt resident
            __syncthreads();       // all copies visible; prev buf consumed
            if (kt < 3) {
                issue_s(scur, kt + 1, (kt + 1) & 1);
                issue_w(wh, wt, kt + 1, (kt + 1) & 1);
                CP_COMMIT();
            }

            const int cur = kt & 1;
            const float* Sb = smem + cur * BUFSZ + ks;
            const float* Wb = smem + cur * BUFSZ + WT_OFFS + ks;

            #pragma unroll
            for (int k4 = 0; k4 < 4; k4++) {
                ulonglong2 wv[4];
                #pragma unroll
                for (int j = 0; j < 4; j++)
                    wv[j] = *(const ulonglong2*)(Wb + (ggrp + 4 * j) * SP + k4 * 4);
                #pragma unroll
                for (int i = 0; i < 8; i++) {
                    ulonglong2 sv = *(const ulonglong2*)(Sb + (bgrp + 8 * i) * SP + k4 * 4);
                    #pragma unroll
                    for (int j = 0; j < 4; j++) {
                        ffma2(acc[i][j], sv.x, wv[j].x);
                        ffma2(acc[i][j], sv.y, wv[j].y);
                    }
                }
            }
        }

        // ---- write per-warp partials (alias buf0 state region) ------------
        __syncthreads();   // all warps done with tile3 (buf1) & buf0 free
        #pragma unroll
        for (int i = 0; i < 8; i++) {
            const int b = bgrp + 8 * i;
            #pragma unroll
            for (int j = 0; j < 4; j++) {
                const int gc = ggrp + 4 * j;
                smem[gc * PP + warp * 64 + b] = f32x2_sum(acc[i][j]);
            }
        }
        __syncthreads();

        // ---- reduction + fused epilogue: thread -> one (b, g) --------------
        {
            const int bb = tid >> 3;          // 0..63
            const int gq = tid & 7;           // 0..7
            const int g  = gb * 8 + gq;

            float ph = 0.f, pt = 0.f;
            #pragma unroll
            for (int w = 0; w < 16; w++) {
                ph += smem[gq * PP + w * 64 + bb];
                pt += smem[(8 + gq) * PP + w * 64 + bb];
            }
            ph += rh_b[l * H_ + g];
            pt += rt_b[l * H_ + g];
            if (l == 0) {
                const float* xw = g_xw + (size_t)(t * B_ + bb) * (2 * H_);
                ph += xw[g];
                pt += xw[H_ + g];
            }
            const float so = scur[(size_t)bb * H_ + g];
            const float h  = tanhf(ph);
            const float tt = 1.0f / (1.0f + expf(-pt));
            const float sn = fmaf(h - so, tt, so);
            snxt[(size_t)bb * H_ + g] = sn;
            if (l == L_ - 1) {
                out[((size_t)bb * T_ + t) * H_ + g] = sn;
                if (t == T_ - 1)
                    out[(size_t)B_ * T_ * H_ + (size_t)bb * H_ + g] = sn;
            }
        }

        if (++l == L_) { l = 0; ++t; }

        if (step != T_ * L_ - 1) {
            // next step's WEIGHT tile 0 (read-only; WT(0) region is idle)
            issue_w(whbase + (size_t)l * H_ * H_,
                    wtbase + (size_t)l * H_ * H_, 0, 0);
            CP_COMMIT();

            grid_sync_persistent();

            // state published; its tile 0 overwrites the consumed partials
            issue_s(g_state[(step + 1) & 1], 0, 0);
            CP_COMMIT();
        }
    }
}

// ---------------------------------------------------------------------------
extern "C" void kernel_launch(void* const* d_in, const int* in_sizes, int n_in,
                              void* d_out, int out_size)
{
    const float* input = (const float*)d_in[0];
    const float* s0    = (const float*)d_in[1];
    const float* w_h   = (const float*)d_in[2];
    const float* w_t   = (const float*)d_in[3];
    const float* rh_w  = (const float*)d_in[4];
    const float* rh_b  = (const float*)d_in[5];
    const float* rt_w  = (const float*)d_in[6];
    const float* rt_b  = (const float*)d_in[7];
    float* out = (float*)d_out;

    static bool attr_set = false;
    if (!attr_set) {
        cudaFuncSetAttribute(rhn_persistent_kernel,
                             cudaFuncAttributeMaxDynamicSharedMemorySize,
                             SMEM_FLOATS * sizeof(float));
        attr_set = true;
    }

    cudaMemcpyToSymbolAsync(g_state, s0, (size_t)B_ * H_ * sizeof(float), 0,
                            cudaMemcpyDeviceToDevice);

    {
        dim3 grid(16, 256);
        xw_gemm_kernel<<<grid, 256>>>(input, w_h, w_t);
    }

    rhn_persistent_kernel<<<NBLK, TPB, SMEM_FLOATS * sizeof(float)>>>(
        rh_w, rh_b, rt_w, rt_b, out);
}

// round 7
// speedup vs baseline: 1.4693x; 1.4693x over previous
#include <cuda_runtime.h>
#include <math.h>
#include <stdint.h>

#define B_  64
#define T_  512
#define IN_ 1024
#define H_  1024
#define L_  5

#define NBLK 128          // persistent CTAs, 1 per SM
#define TPB  256          // 8 warps
#define NGRP 4            // independent batch groups
#define CPG  32           // CTAs per group
#define BPG  16           // batch rows per group
#define GPC  32           // g-columns per CTA (per gate)

typedef unsigned long long ull;

// smem geometry (floats)
#define SSP   1032                     // state pitch (16 rows x full K)
#define SST   (16 * SSP)               // 16512 state floats
#define WSP   132                      // weight tile pitch (128 k + pad)
#define WBUF  (64 * WSP)               // 8448 floats per ring buffer
#define RING  3
#define PART  (8 * 16 * 64)            // 8192 partial floats (8 warps x 16b x 64gc)
#define SMEM_FLOATS (SST + RING * WBUF + PART)   // 50048 -> 200KB

// Static device scratch:
__device__ float g_xw[(size_t)B_ * T_ * 2 * H_];   // [whx|wtx], time-major
__device__ float g_state[2][B_ * H_];              // double-buffered state
__device__ unsigned g_arr[NGRP * 64];              // per-group arrive counters (256B apart)
__device__ unsigned g_gen[NGRP * 64];              // per-group generation

// ---- packed fp32x2 helpers (sm_103a FFMA2) --------------------------------
__device__ __forceinline__ void ffma2(ull& d, ull a, ull b) {
    asm("fma.rn.f32x2 %0, %1, %2, %0;" : "+l"(d) : "l"(a), "l"(b));
}
__device__ __forceinline__ ull packff(float x, float y) {
    ull r; asm("mov.b64 %0, {%1, %2};" : "=l"(r) : "f"(x), "f"(y)); return r;
}
__device__ __forceinline__ float f32x2_sum(ull v) {
    union { ull u; float2 f; } c; c.u = v; return c.f.x + c.f.y;
}

// ---- cp.async helpers -----------------------------------------------------
__device__ __forceinline__ void cp16_cg(uint32_t dst, const void* src) {
    asm volatile("cp.async.cg.shared.global [%0], [%1], 16;" :: "r"(dst), "l"(src) : "memory");
}
__device__ __forceinline__ void cp16_ca(uint32_t dst, const void* src) {
    asm volatile("cp.async.ca.shared.global [%0], [%1], 16;" :: "r"(dst), "l"(src) : "memory");
}
#define CP_COMMIT() asm volatile("cp.async.commit_group;" ::: "memory")
#define CP_WAIT0()  asm volatile("cp.async.wait_group 0;" ::: "memory")
#define CP_WAIT1()  asm volatile("cp.async.wait_group 1;" ::: "memory")

// ---------------------------------------------------------------------------
__global__ void reset_barrier_kernel()
{
    int i = threadIdx.x;
    if (i < NGRP * 64) { g_arr[i] = 0u; g_gen[i] = 0u; }
}

// ---------------------------------------------------------------------------
// Input GEMM with FFMA2 (unchanged)
// ---------------------------------------------------------------------------
__global__ __launch_bounds__(256) void xw_gemm_kernel(
    const float* __restrict__ x,
    const float* __restrict__ w_h,
    const float* __restrict__ w_t)
{
    __shared__ float As[8][132];
    __shared__ float Bs[8][132];

    const int jb  = blockIdx.x;
    const int rb  = blockIdx.y;
    const int tid = threadIdx.x;
    const int tx  = tid % 16;
    const int ty  = tid / 16;

    const int jbase = jb * 128;
    const float* W  = (jbase < H_) ? w_h : w_t;
    const int  joff = jbase % H_;

    ull acc2[8][4];
    #pragma unroll
    for (int i = 0; i < 8; i++)
        #pragma unroll
        for (int j = 0; j < 4; j++) acc2[i][j] = 0ull;

    const int arow = tid / 2;
    const int ak   = (tid % 2) * 4;
    const int r    = rb * 128 + arow;
    const int xrow = (r % B_) * T_ + (r / B_);
    const float* aptr = x + (size_t)xrow * IN_ + ak;

    const int bk = tid / 32;
    const int bj = (tid % 32) * 4;
    const float* bptr = W + (size_t)bk * H_ + joff + bj;

    for (int kt = 0; kt < IN_; kt += 8) {
        float4 av = *(const float4*)(aptr + kt);
        float4 bv = *(const float4*)(bptr + (size_t)kt * H_);
        __syncthreads();
        As[ak + 0][arow] = av.x;
        As[ak + 1][arow] = av.y;
        As[ak + 2][arow] = av.z;
        As[ak + 3][arow] = av.w;
        *(float4*)&Bs[bk][bj] = bv;
        __syncthreads();

        #pragma unroll
        for (int k = 0; k < 8; k++) {
            float a[8];
            #pragma unroll
            for (int i = 0; i < 8; i++) a[i] = As[k][ty * 8 + i];
            ulonglong2 bv0 = *(const ulonglong2*)&Bs[k][tx * 8];
            ulonglong2 bv1 = *(const ulonglong2*)&Bs[k][tx * 8 + 4];
            #pragma unroll
            for (int i = 0; i < 8; i++) {
                ull ap = packff(a[i], a[i]);
                ffma2(acc2[i][0], ap, bv0.x);
                ffma2(acc2[i][1], ap, bv0.y);
                ffma2(acc2[i][2], ap, bv1.x);
                ffma2(acc2[i][3], ap, bv1.y);
            }
        }
    }

    #pragma unroll
    for (int i = 0; i < 8; i++) {
        int rr = rb * 128 + ty * 8 + i;
        float* cp = g_xw + (size_t)rr * (2 * H_) + jbase + tx * 8;
        union { ull u; float2 f; } c0, c1, c2, c3;
        c0.u = acc2[i][0]; c1.u = acc2[i][1]; c2.u = acc2[i][2]; c3.u = acc2[i][3];
        *(float4*)(cp + 0) = make_float4(c0.f.x, c0.f.y, c1.f.x, c1.f.y);
        *(float4*)(cp + 4) = make_float4(c2.f.x, c2.f.y, c3.f.x, c3.f.y);
    }
}

// ---------------------------------------------------------------------------
// Fence-free scoped sub-barrier: 32 CTAs of one batch group, monotonic counters.
// Release/acquire atomics order the st.cg state stores; no CCTL.IVALL.
// ---------------------------------------------------------------------------
__device__ __forceinline__ void group_sync(int gr, int step)
{
    __syncthreads();
    if (threadIdx.x == 0) {
        unsigned* arr = &g_arr[gr * 64];
        unsigned* gen = &g_gen[gr * 64];
        unsigned old;
        asm volatile("atom.acq_rel.gpu.global.add.u32 %0, [%1], 1;"
                     : "=r"(old) : "l"(arr) : "memory");
        if (old == (unsigned)(step * CPG + CPG - 1)) {
            asm volatile("st.release.gpu.global.u32 [%0], %1;"
                         :: "l"(gen), "r"((unsigned)(step + 1)) : "memory");
        } else {
            unsigned cur;
            do {
                asm volatile("ld.acquire.gpu.global.u32 %0, [%1];"
                             : "=r"(cur) : "l"(gen) : "memory");
            } while (cur <= (unsigned)step);
        }
    }
    __syncthreads();
}

// ---------------------------------------------------------------------------
// Persistent recurrent kernel.
// Grid: 4 independent groups x 32 CTAs. CTA: 16 b-rows x 32 g (both gates).
// 8 warps, K-split (warp w owns k-slice w*16 within each 128-k weight tile).
// Thread: 4 b x 8 gate-cols, f32x2 accumulation. Weight ring depth 3.
// ---------------------------------------------------------------------------
__global__ __launch_bounds__(TPB) void rhn_persistent_kernel(
    const float* __restrict__ rh_w, const float* __restrict__ rh_b,
    const float* __restrict__ rt_w, const float* __restrict__ rt_b,
    float* __restrict__ out)
{
    extern __shared__ float smem[];
    float* s_s  = smem;                       // [16][SSP]
    float* ring = smem + SST;                 // [3][64][WSP]
    float* part = smem + SST + RING * WBUF;   // [8][16][64]
    const uint32_t ss_u32 = (uint32_t)__cvta_generic_to_shared(s_s);
    const uint32_t rg_u32 = (uint32_t)__cvta_generic_to_shared(ring);

    const int tid   = threadIdx.x;
    const int warp  = tid >> 5;               // 0..7
    const int lane  = tid & 31;
    const int bgrp  = lane >> 3;              // 0..3
    const int gcgrp = lane & 7;               // 0..7
    const int gb    = blockIdx.x;             // 0..127
    const int gr    = gb >> 5;                // group 0..3
    const int c32   = gb & 31;                // CTA within group
    const int bbase = gr * BPG;
    const int gbase = c32 * GPC;

    // state copy mapping: row rs = tid>>4 (16 rows), 16 f4 per thread
    const int rs = tid >> 4;
    const int sc = (tid & 15) * 4;            // float col base, stride 64
    // weight copy mapping: row rw = tid>>2 (64 rows), 8 f4 per thread
    const int rw = tid >> 2;
    const int wc = (tid & 3) * 4;             // float col base, stride 16
    const int w_gate = rw >> 5;               // 0 = h, 1 = t
    const int w_gl   = rw & 31;

    auto issue_state = [&](const float* scur) {
        const float* src = scur + (size_t)(bbase + rs) * H_ + sc;
        uint32_t dst = ss_u32 + (uint32_t)(rs * SSP + sc) * 4;
        #pragma unroll
        for (int ii = 0; ii < 16; ii++)
            cp16_cg(dst + ii * 64 * 4, src + ii * 64);
        CP_COMMIT();
    };
    auto issue_w = [&](const float* wh, const float* wt, int kt) {
        const float* src = (w_gate ? wt : wh) + (size_t)(gbase + w_gl) * H_ + kt * 128 + wc;
        uint32_t dst = rg_u32 + (uint32_t)((kt % RING) * WBUF + rw * WSP + wc) * 4;
        #pragma unroll
        for (int ii = 0; ii < 8; ii++)
            cp16_ca(dst + ii * 16 * 4, src + ii * 16);
        CP_COMMIT();
    };

    // prologue for step 0: weight tiles 0,1 then state
    {
        const float* wh0 = rh_w;   // l = 0
        const float* wt0 = rt_w;
        issue_w(wh0, wt0, 0);
        issue_w(wh0, wt0, 1);
        issue_state(g_state[0]);
    }

    int t = 0, l = 0;
    for (int step = 0; step < T_ * L_; step++) {
        const int pin = step & 1;
        const float* scur = g_state[pin];
        float*       snxt = g_state[pin ^ 1];
        const float* wh = rh_w + (size_t)l * H_ * H_;
        const float* wt = rt_w + (size_t)l * H_ * H_;

        ull acc[4][8];
        #pragma unroll
        for (int i = 0; i < 4; i++)
            #pragma unroll
            for (int j = 0; j < 8; j++) acc[i][j] = 0ull;

        // ---- mainloop: 8 weight k-tiles, ring-3 ---------------------------
        #pragma unroll
        for (int kt = 0; kt < 8; kt++) {
            if (kt == 0 || kt == 7) { CP_WAIT0(); } else { CP_WAIT1(); }
            __syncthreads();                   // tile kt (and state) ready; buf (kt-1)%3 free
            if (kt < 6) issue_w(wh, wt, kt + 2);

            const float* Sb = s_s + kt * 128 + warp * 16;
            const float* Wb = ring + (kt % RING) * WBUF + warp * 16;

            #pragma unroll
            for (int k4 = 0; k4 < 4; k4++) {
                ulonglong2 sv[4];
                #pragma unroll
                for (int i = 0; i < 4; i++)
                    sv[i] = *(const ulonglong2*)(Sb + (bgrp + 4 * i) * SSP + k4 * 4);
                #pragma unroll
                for (int j = 0; j < 8; j++) {
                    ulonglong2 wv = *(const ulonglong2*)(Wb + (gcgrp + 8 * j) * WSP + k4 * 4);
                    #pragma unroll
                    for (int i = 0; i < 4; i++) {
                        ffma2(acc[i][j], sv[i].x, wv.x);
                        ffma2(acc[i][j], sv[i].y, wv.y);
                    }
                }
            }
        }

        // ---- partials -----------------------------------------------------
        __syncthreads();                       // all warps done with all tiles
        #pragma unroll
        for (int i = 0; i < 4; i++) {
            const int b = bgrp + 4 * i;
            #pragma unroll
            for (int j = 0; j < 8; j++)
                part[warp * 1024 + b * 64 + (gcgrp + 8 * j)] = f32x2_sum(acc[i][j]);
        }
        __syncthreads();

        // advance indices, pre-issue next step's weight tiles 0,1 (read-only)
        int tn = t, ln = l + 1;
        if (ln == L_) { ln = 0; tn = t + 1; }
        const bool last = (step == T_ * L_ - 1);
        if (!last) {
            const float* whn = rh_w + (size_t)ln * H_ * H_;
            const float* wtn = rt_w + (size_t)ln * H_ * H_;
            issue_w(whn, wtn, 0);
            issue_w(whn, wtn, 1);
        }

        // ---- reduction + fused epilogue (2 outputs per thread) ------------
        #pragma unroll
        for (int p = 0; p < 2; p++) {
            const int q  = tid * 2 + p;        // 0..511
            const int bl = q >> 5;             // 0..15
            const int gl = q & 31;             // 0..31
            const int bglob = bbase + bl;
            const int g     = gbase + gl;

            float ph = 0.f, pt = 0.f;
            #pragma unroll
            for (int w = 0; w < 8; w++) {
                ph += part[w * 1024 + bl * 64 + gl];
                pt += part[w * 1024 + bl * 64 + 32 + gl];
            }
            ph += rh_b[l * H_ + g];
            pt += rt_b[l * H_ + g];
            if (l == 0) {
                const float* xw = g_xw + (size_t)(t * B_ + bglob) * (2 * H_);
                ph += xw[g];
                pt += xw[H_ + g];
            }
            const float so = __ldcg(&scur[(size_t)bglob * H_ + g]);
            const float h  = tanhf(ph);
            const float tt = 1.0f / (1.0f + expf(-pt));
            const float sn = fmaf(h - so, tt, so);
            __stcg(&snxt[(size_t)bglob * H_ + g], sn);
            if (l == L_ - 1) {
                out[((size_t)bglob * T_ + t) * H_ + g] = sn;
                if (t == T_ - 1)
                    out[(size_t)B_ * T_ * H_ + (size_t)bglob * H_ + g] = sn;
            }
        }

        t = tn; l = ln;

        if (!last) {
            group_sync(gr, step);              // scoped, fence-free
            issue_state(g_state[(step + 1) & 1]);
        }
    }
}

// ---------------------------------------------------------------------------
extern "C" void kernel_launch(void* const* d_in, const int* in_sizes, int n_in,
                              void* d_out, int out_size)
{
    const float* input = (const float*)d_in[0];
    const float* s0    = (const float*)d_in[1];
    const float* w_h   = (const float*)d_in[2];
    const float* w_t   = (const float*)d_in[3];
    const float* rh_w  = (const float*)d_in[4];
    const float* rh_b  = (const float*)d_in[5];
    const float* rt_w  = (const float*)d_in[6];
    const float* rt_b  = (const float*)d_in[7];
    float* out = (float*)d_out;

    static bool attr_set = false;
    if (!attr_set) {
        cudaFuncSetAttribute(rhn_persistent_kernel,
                             cudaFuncAttributeMaxDynamicSharedMemorySize,
                             SMEM_FLOATS * sizeof(float));
        attr_set = true;
    }

    reset_barrier_kernel<<<1, 256>>>();

    cudaMemcpyToSymbolAsync(g_state, s0, (size_t)B_ * H_ * sizeof(float), 0,
                            cudaMemcpyDeviceToDevice);

    {
        dim3 grid(16, 256);
        xw_gemm_kernel<<<grid, 256>>>(input, w_h, w_t);
    }

    rhn_persistent_kernel<<<NBLK, TPB, SMEM_FLOATS * sizeof(float)>>>(
        rh_w, rh_b, rt_w, rt_b, out);
}

// round 8
// speedup vs baseline: 1.4795x; 1.0070x over previous
#include <cuda_runtime.h>
#include <math.h>
#include <stdint.h>

#define B_  64
#define T_  512
#define IN_ 1024
#define H_  1024
#define L_  5

#define NBLK 128          // persistent CTAs, 1 per SM
#define TPB  256          // 8 warps
#define NGRP 4            // independent batch groups
#define CPG  32           // CTAs per group
#define BPG  16           // batch rows per group
#define GPC  32           // g-columns per CTA (per gate)

typedef unsigned long long ull;

// smem geometry (floats)
#define SSP   1032                     // state pitch (16 rows x full K)
#define SST   (16 * SSP)               // 16512 state floats
#define WSP   132                      // weight tile pitch (128 k + pad)
#define WBUF  (64 * WSP)               // 8448 floats per ring buffer
#define RING  3
#define PART  (8 * 16 * 64)            // 8192 partial floats (8 warps x 16b x 64gc)
#define SMEM_FLOATS (SST + RING * WBUF + PART)   // 50048 -> 200KB

// Static device scratch:
__device__ float g_xw[(size_t)B_ * T_ * 2 * H_];   // [whx|wtx], time-major
__device__ float g_state[2][B_ * H_];              // double-buffered state
__device__ unsigned g_arr[NGRP * 64];              // per-group arrive counters (256B apart)
__device__ unsigned g_gen[NGRP * 64];              // per-group generation

// ---- packed fp32x2 helpers (sm_103a FFMA2) --------------------------------
__device__ __forceinline__ void ffma2(ull& d, ull a, ull b) {
    asm("fma.rn.f32x2 %0, %1, %2, %0;" : "+l"(d) : "l"(a), "l"(b));
}
__device__ __forceinline__ ull packff(float x, float y) {
    ull r; asm("mov.b64 %0, {%1, %2};" : "=l"(r) : "f"(x), "f"(y)); return r;
}
__device__ __forceinline__ float f32x2_sum(ull v) {
    union { ull u; float2 f; } c; c.u = v; return c.f.x + c.f.y;
}

// ---- cp.async helpers -----------------------------------------------------
__device__ __forceinline__ void cp16_cg(uint32_t dst, const void* src) {
    asm volatile("cp.async.cg.shared.global [%0], [%1], 16;" :: "r"(dst), "l"(src) : "memory");
}
__device__ __forceinline__ void cp16_ca(uint32_t dst, const void* src) {
    asm volatile("cp.async.ca.shared.global [%0], [%1], 16;" :: "r"(dst), "l"(src) : "memory");
}
#define CP_COMMIT() asm volatile("cp.async.commit_group;" ::: "memory")
#define CP_WAIT0()  asm volatile("cp.async.wait_group 0;" ::: "memory")
#define CP_WAIT1()  asm volatile("cp.async.wait_group 1;" ::: "memory")

// ---------------------------------------------------------------------------
__global__ void reset_barrier_kernel()
{
    int i = threadIdx.x;
    if (i < NGRP * 64) { g_arr[i] = 0u; g_gen[i] = 0u; }
}

// ---------------------------------------------------------------------------
// Input GEMM with FFMA2 (unchanged)
// ---------------------------------------------------------------------------
__global__ __launch_bounds__(256) void xw_gemm_kernel(
    const float* __restrict__ x,
    const float* __restrict__ w_h,
    const float* __restrict__ w_t)
{
    __shared__ float As[8][132];
    __shared__ float Bs[8][132];

    const int jb  = blockIdx.x;
    const int rb  = blockIdx.y;
    const int tid = threadIdx.x;
    const int tx  = tid % 16;
    const int ty  = tid / 16;

    const int jbase = jb * 128;
    const float* W  = (jbase < H_) ? w_h : w_t;
    const int  joff = jbase % H_;

    ull acc2[8][4];
    #pragma unroll
    for (int i = 0; i < 8; i++)
        #pragma unroll
        for (int j = 0; j < 4; j++) acc2[i][j] = 0ull;

    const int arow = tid / 2;
    const int ak   = (tid % 2) * 4;
    const int r    = rb * 128 + arow;
    const int xrow = (r % B_) * T_ + (r / B_);
    const float* aptr = x + (size_t)xrow * IN_ + ak;

    const int bk = tid / 32;
    const int bj = (tid % 32) * 4;
    const float* bptr = W + (size_t)bk * H_ + joff + bj;

    for (int kt = 0; kt < IN_; kt += 8) {
        float4 av = *(const float4*)(aptr + kt);
        float4 bv = *(const float4*)(bptr + (size_t)kt * H_);
        __syncthreads();
        As[ak + 0][arow] = av.x;
        As[ak + 1][arow] = av.y;
        As[ak + 2][arow] = av.z;
        As[ak + 3][arow] = av.w;
        *(float4*)&Bs[bk][bj] = bv;
        __syncthreads();

        #pragma unroll
        for (int k = 0; k < 8; k++) {
            float a[8];
            #pragma unroll
            for (int i = 0; i < 8; i++) a[i] = As[k][ty * 8 + i];
            ulonglong2 bv0 = *(const ulonglong2*)&Bs[k][tx * 8];
            ulonglong2 bv1 = *(const ulonglong2*)&Bs[k][tx * 8 + 4];
            #pragma unroll
            for (int i = 0; i < 8; i++) {
                ull ap = packff(a[i], a[i]);
                ffma2(acc2[i][0], ap, bv0.x);
                ffma2(acc2[i][1], ap, bv0.y);
                ffma2(acc2[i][2], ap, bv1.x);
                ffma2(acc2[i][3], ap, bv1.y);
            }
        }
    }

    #pragma unroll
    for (int i = 0; i < 8; i++) {
        int rr = rb * 128 + ty * 8 + i;
        float* cp = g_xw + (size_t)rr * (2 * H_) + jbase + tx * 8;
        union { ull u; float2 f; } c0, c1, c2, c3;
        c0.u = acc2[i][0]; c1.u = acc2[i][1]; c2.u = acc2[i][2]; c3.u = acc2[i][3];
        *(float4*)(cp + 0) = make_float4(c0.f.x, c0.f.y, c1.f.x, c1.f.y);
        *(float4*)(cp + 4) = make_float4(c2.f.x, c2.f.y, c3.f.x, c3.f.y);
    }
}

// ---------------------------------------------------------------------------
// Fence-free scoped sub-barrier: 32 CTAs of one batch group, monotonic counters.
// Release/acquire atomics order the st.cg state stores; no CCTL.IVALL.
// ---------------------------------------------------------------------------
__device__ __forceinline__ void group_sync(int gr, int step)
{
    __syncthreads();
    if (threadIdx.x == 0) {
        unsigned* arr = &g_arr[gr * 64];
        unsigned* gen = &g_gen[gr * 64];
        unsigned old;
        asm volatile("atom.acq_rel.gpu.global.add.u32 %0, [%1], 1;"
                     : "=r"(old) : "l"(arr) : "memory");
        if (old == (unsigned)(step * CPG + CPG - 1)) {
            asm volatile("st.release.gpu.global.u32 [%0], %1;"
                         :: "l"(gen), "r"((unsigned)(step + 1)) : "memory");
        } else {
            unsigned cur;
            do {
                asm volatile("ld.acquire.gpu.global.u32 %0, [%1];"
                             : "=r"(cur) : "l"(gen) : "memory");
            } while (cur <= (unsigned)step);
        }
    }
    __syncthreads();
}

// ---------------------------------------------------------------------------
// Persistent recurrent kernel.
// Grid: 4 independent groups x 32 CTAs. CTA: 16 b-rows x 32 g (both gates).
// 8 warps, K-split (warp w owns k-slice w*16 within each 128-k weight tile).
// Thread: 4 b x 8 gate-cols, f32x2 accumulation. Weight ring depth 3.
// ---------------------------------------------------------------------------
__global__ __launch_bounds__(TPB) void rhn_persistent_kernel(
    const float* __restrict__ rh_w, const float* __restrict__ rh_b,
    const float* __restrict__ rt_w, const float* __restrict__ rt_b,
    float* __restrict__ out)
{
    extern __shared__ float smem[];
    float* s_s  = smem;                       // [16][SSP]
    float* ring = smem + SST;                 // [3][64][WSP]
    float* part = smem + SST + RING * WBUF;   // [8][16][64]
    const uint32_t ss_u32 = (uint32_t)__cvta_generic_to_shared(s_s);
    const uint32_t rg_u32 = (uint32_t)__cvta_generic_to_shared(ring);

    const int tid   = threadIdx.x;
    const int warp  = tid >> 5;               // 0..7
    const int lane  = tid & 31;
    const int bgrp  = lane >> 3;              // 0..3
    const int gcgrp = lane & 7;               // 0..7
    const int gb    = blockIdx.x;             // 0..127
    const int gr    = gb >> 5;                // group 0..3
    const int c32   = gb & 31;                // CTA within group
    const int bbase = gr * BPG;
    const int gbase = c32 * GPC;

    // state copy mapping: row rs = tid>>4 (16 rows), 16 f4 per thread
    const int rs = tid >> 4;
    const int sc = (tid & 15) * 4;            // float col base, stride 64
    // weight copy mapping: row rw = tid>>2 (64 rows), 8 f4 per thread
    const int rw = tid >> 2;
    const int wc = (tid & 3) * 4;             // float col base, stride 16
    const int w_gate = rw >> 5;               // 0 = h, 1 = t
    const int w_gl   = rw & 31;

    auto issue_state = [&](const float* scur) {
        const float* src = scur + (size_t)(bbase + rs) * H_ + sc;
        uint32_t dst = ss_u32 + (uint32_t)(rs * SSP + sc) * 4;
        #pragma unroll
        for (int ii = 0; ii < 16; ii++)
            cp16_cg(dst + ii * 64 * 4, src + ii * 64);
        CP_COMMIT();
    };
    auto issue_w = [&](const float* wh, const float* wt, int kt) {
        const float* src = (w_gate ? wt : wh) + (size_t)(gbase + w_gl) * H_ + kt * 128 + wc;
        uint32_t dst = rg_u32 + (uint32_t)((kt % RING) * WBUF + rw * WSP + wc) * 4;
        #pragma unroll
        for (int ii = 0; ii < 8; ii++)
            cp16_ca(dst + ii * 16 * 4, src + ii * 16);
        CP_COMMIT();
    };

    // prologue for step 0: weight tiles 0,1 then state
    {
        const float* wh0 = rh_w;   // l = 0
        const float* wt0 = rt_w;
        issue_w(wh0, wt0, 0);
        issue_w(wh0, wt0, 1);
        issue_state(g_state[0]);
    }

    int t = 0, l = 0;
    for (int step = 0; step < T_ * L_; step++) {
        const int pin = step & 1;
        const float* scur = g_state[pin];
        float*       snxt = g_state[pin ^ 1];
        const float* wh = rh_w + (size_t)l * H_ * H_;
        const float* wt = rt_w + (size_t)l * H_ * H_;

        ull acc[4][8];
        #pragma unroll
        for (int i = 0; i < 4; i++)
            #pragma unroll
            for (int j = 0; j < 8; j++) acc[i][j] = 0ull;

        // ---- mainloop: 8 weight k-tiles, ring-3 ---------------------------
        #pragma unroll
        for (int kt = 0; kt < 8; kt++) {
            if (kt == 0 || kt == 7) { CP_WAIT0(); } else { CP_WAIT1(); }
            __syncthreads();                   // tile kt (and state) ready; buf (kt-1)%3 free
            if (kt < 6) issue_w(wh, wt, kt + 2);

            const float* Sb = s_s + kt * 128 + warp * 16;
            const float* Wb = ring + (kt % RING) * WBUF + warp * 16;

            #pragma unroll
            for (int k4 = 0; k4 < 4; k4++) {
                ulonglong2 sv[4];
                #pragma unroll
                for (int i = 0; i < 4; i++)
                    sv[i] = *(const ulonglong2*)(Sb + (bgrp + 4 * i) * SSP + k4 * 4);
                #pragma unroll
                for (int j = 0; j < 8; j++) {
                    ulonglong2 wv = *(const ulonglong2*)(Wb + (gcgrp + 8 * j) * WSP + k4 * 4);
                    #pragma unroll
                    for (int i = 0; i < 4; i++) {
                        ffma2(acc[i][j], sv[i].x, wv.x);
                        ffma2(acc[i][j], sv[i].y, wv.y);
                    }
                }
            }
        }

        // ---- partials -----------------------------------------------------
        __syncthreads();                       // all warps done with all tiles
        #pragma unroll
        for (int i = 0; i < 4; i++) {
            const int b = bgrp + 4 * i;
            #pragma unroll
            for (int j = 0; j < 8; j++)
                part[warp * 1024 + b * 64 + (gcgrp + 8 * j)] = f32x2_sum(acc[i][j]);
        }
        __syncthreads();

        // advance indices, pre-issue next step's weight tiles 0,1 (read-only)
        int tn = t, ln = l + 1;
        if (ln == L_) { ln = 0; tn = t + 1; }
        const bool last = (step == T_ * L_ - 1);
        if (!last) {
            const float* whn = rh_w + (size_t)ln * H_ * H_;
            const float* wtn = rt_w + (size_t)ln * H_ * H_;
            issue_w(whn, wtn, 0);
            issue_w(whn, wtn, 1);
        }

        // ---- reduction + fused epilogue (2 outputs per thread) ------------
        #pragma unroll
        for (int p = 0; p < 2; p++) {
            const int q  = tid * 2 + p;        // 0..511
            const int bl = q >> 5;             // 0..15
            const int gl = q & 31;             // 0..31
            const int bglob = bbase + bl;
            const int g     = gbase + gl;

            float ph = 0.f, pt = 0.f;
            #pragma unroll
            for (int w = 0; w < 8; w++) {
                ph += part[w * 1024 + bl * 64 + gl];
                pt += part[w * 1024 + bl * 64 + 32 + gl];
            }
            ph += rh_b[l * H_ + g];
            pt += rt_b[l * H_ + g];
            if (l == 0) {
                const float* xw = g_xw + (size_t)(t * B_ + bglob) * (2 * H_);
                ph += xw[g];
                pt += xw[H_ + g];
            }
            const float so = __ldcg(&scur[(size_t)bglob * H_ + g]);
            const float h  = tanhf(ph);
            const float tt = 1.0f / (1.0f + expf(-pt));
            const float sn = fmaf(h - so, tt, so);
            __stcg(&snxt[(size_t)bglob * H_ + g], sn);
            if (l == L_ - 1) {
                out[((size_t)bglob * T_ + t) * H_ + g] = sn;
                if (t == T_ - 1)
                    out[(size_t)B_ * T_ * H_ + (size_t)bglob * H_ + g] = sn;
            }
        }

        t = tn; l = ln;

        if (!last) {
            group_sync(gr, step);              // scoped, fence-free
            issue_state(g_state[(step + 1) & 1]);
        }
    }
}

// ---------------------------------------------------------------------------
extern "C" void kernel_launch(void* const* d_in, const int* in_sizes, int n_in,
                              void* d_out, int out_size)
{
    const float* input = (const float*)d_in[0];
    const float* s0    = (const float*)d_in[1];
    const float* w_h   = (const float*)d_in[2];
    const float* w_t   = (const float*)d_in[3];
    const float* rh_w  = (const float*)d_in[4];
    const float* rh_b  = (const float*)d_in[5];
    const float* rt_w  = (const float*)d_in[6];
    const float* rt_b  = (const float*)d_in[7];
    float* out = (float*)d_out;

    static bool attr_set = false;
    if (!attr_set) {
        cudaFuncSetAttribute(rhn_persistent_kernel,
                             cudaFuncAttributeMaxDynamicSharedMemorySize,
                             SMEM_FLOATS * sizeof(float));
        attr_set = true;
    }

    reset_barrier_kernel<<<1, 256>>>();

    cudaMemcpyToSymbolAsync(g_state, s0, (size_t)B_ * H_ * sizeof(float), 0,
                            cudaMemcpyDeviceToDevice);

    {
        dim3 grid(16, 256);
        xw_gemm_kernel<<<grid, 256>>>(input, w_h, w_t);
    }

    rhn_persistent_kernel<<<NBLK, TPB, SMEM_FLOATS * sizeof(float)>>>(
        rh_w, rh_b, rt_w, rt_b, out);
}